// round 2
// baseline (speedup 1.0000x reference)
#include <cuda_runtime.h>
#include <cstddef>

// GRU_83133386982146: 2-layer GRU (H=10) + per-step linear 10->1.
// B=1024 warps, one warp per batch row. 30 active lanes = 30 gate rows.
// h0/h1 distributed on lanes 0..9; dots via warp shuffles; gates via
// MUFU.TANH (sigmoid(x) = 0.5*tanh(0.5x)+0.5). x/out buffered per lane,
// coalesced LDG/STG every 32 timesteps.
// R2: split dot-product fma chains into 2 independent partials (ILP).

#define FULL 0xffffffffu

namespace {
constexpr int H = 10;
constexpr int G = 3 * H;   // 30 gate rows
constexpr int T = 2048;
constexpr int B = 1024;
}

__device__ __forceinline__ float fast_tanh(float x) {
    float y;
    asm("tanh.approx.f32 %0, %1;" : "=f"(y) : "f"(x));
    return y;
}
__device__ __forceinline__ float fast_sigmoid(float x) {
    // sigmoid(x) = 0.5 * tanh(0.5 x) + 0.5
    return fmaf(fast_tanh(0.5f * x), 0.5f, 0.5f);
}

__global__ void __launch_bounds__(32)
gru_warp_kernel(const float* __restrict__ x,
                const float* __restrict__ Wih0, const float* __restrict__ Whh0,
                const float* __restrict__ bih0, const float* __restrict__ bhh0,
                const float* __restrict__ Wih1, const float* __restrict__ Whh1,
                const float* __restrict__ bih1, const float* __restrict__ bhh1,
                const float* __restrict__ Wlin, const float* __restrict__ blin,
                float* __restrict__ out)
{
    const int b = blockIdx.x;
    const int lane = threadIdx.x;
    const int j = (lane < G) ? lane : (G - 1);   // clamp lanes 30,31
    const bool is_n = (j >= 2 * H);              // n-gate rows 20..29

    // Per-lane weight rows in registers.
    float whh0[H], wih1[H], whh1[H];
#pragma unroll
    for (int k = 0; k < H; k++) {
        whh0[k] = Whh0[j * H + k];
        wih1[k] = Wih1[j * H + k];
        whh1[k] = Whh1[j * H + k];
    }
    const float wih0 = Wih0[j];
    // r/z gates: biases fold together; n gate: bhh must stay inside r*(...)
    const float bx0 = bih0[j] + (is_n ? 0.0f : bhh0[j]);
    const float bh0 = is_n ? bhh0[j] : 0.0f;
    const float bx1 = bih1[j] + (is_n ? 0.0f : bhh1[j]);
    const float bh1 = is_n ? bhh1[j] : 0.0f;
    const float wlin = (lane < H) ? Wlin[lane] : 0.0f;
    const float bl = blin[0];

    const float* xrow = x + (size_t)b * T;
    float* orow = out + (size_t)b * T;

    float h0 = 0.0f, h1 = 0.0f;     // valid on lanes 0..9 (read via shfl only)
    float xbuf = 0.0f, obuf = 0.0f;

    const int ridx = (lane >= 2 * H) ? (lane - 2 * H) : 0;  // n-lanes fetch r
    const int zidx = (lane + H) & 31;                       // lanes 0..9 fetch z
    const int nidx = (lane + 2 * H) & 31;                   // lanes 0..9 fetch n

    for (int t = 0; t < T; t++) {
        if ((t & 31) == 0) xbuf = xrow[t + lane];           // coalesced refill
        const float xt = __shfl_sync(FULL, xbuf, t & 31);

        // ---------------- layer 0 ----------------
        float acc_a = bh0, acc_b = 0.0f;
#pragma unroll
        for (int k = 0; k < H; k += 2) {
            acc_a = fmaf(whh0[k],     __shfl_sync(FULL, h0, k),     acc_a);
            acc_b = fmaf(whh0[k + 1], __shfl_sync(FULL, h0, k + 1), acc_b);
        }
        const float acc = acc_a + acc_b;
        const float px = fmaf(wih0, xt, bx0);
        const float sg = fast_sigmoid(px + acc);            // r/z lanes valid
        const float r  = __shfl_sync(FULL, sg, ridx);
        const float nv = fast_tanh(fmaf(r, acc, px));       // n lanes valid
        const float z  = __shfl_sync(FULL, sg, zidx);
        const float nn = __shfl_sync(FULL, nv, nidx);
        h0 = fmaf(z, h0 - nn, nn);                          // (1-z)*n + z*h

        // ---------------- layer 1 ----------------
        float ax_a = bx1, ax_b = 0.0f;
        float ah_a = bh1, ah_b = 0.0f;
#pragma unroll
        for (int k = 0; k < H; k += 2) {
            const float h0a = __shfl_sync(FULL, h0, k);
            const float h0b = __shfl_sync(FULL, h0, k + 1);
            const float h1a = __shfl_sync(FULL, h1, k);
            const float h1b = __shfl_sync(FULL, h1, k + 1);
            ax_a = fmaf(wih1[k],     h0a, ax_a);
            ax_b = fmaf(wih1[k + 1], h0b, ax_b);
            ah_a = fmaf(whh1[k],     h1a, ah_a);
            ah_b = fmaf(whh1[k + 1], h1b, ah_b);
        }
        const float accx = ax_a + ax_b;
        const float acch = ah_a + ah_b;
        const float sg1 = fast_sigmoid(accx + acch);
        const float r1  = __shfl_sync(FULL, sg1, ridx);
        const float nv1 = fast_tanh(fmaf(r1, acch, accx));
        const float z1  = __shfl_sync(FULL, sg1, zidx);
        const float nn1 = __shfl_sync(FULL, nv1, nidx);
        h1 = fmaf(z1, h1 - nn1, nn1);

        // -------- linear 10->1 + warp reduce --------
        float c = wlin * h1;                                // 0 on lanes >= 10
#pragma unroll
        for (int off = 16; off >= 1; off >>= 1)
            c += __shfl_xor_sync(FULL, c, off);
        const float val = c + bl;
        if ((t & 31) == lane) obuf = val;
        if ((t & 31) == 31) orow[(t & ~31) + lane] = obuf;  // coalesced store
    }
}

extern "C" void kernel_launch(void* const* d_in, const int* in_sizes, int n_in,
                              void* d_out, int out_size) {
    (void)in_sizes; (void)n_in; (void)out_size;
    const float* x    = (const float*)d_in[0];
    const float* Wih0 = (const float*)d_in[1];
    const float* Whh0 = (const float*)d_in[2];
    const float* bih0 = (const float*)d_in[3];
    const float* bhh0 = (const float*)d_in[4];
    const float* Wih1 = (const float*)d_in[5];
    const float* Whh1 = (const float*)d_in[6];
    const float* bih1 = (const float*)d_in[7];
    const float* bhh1 = (const float*)d_in[8];
    const float* Wlin = (const float*)d_in[9];
    const float* blin = (const float*)d_in[10];
    float* out = (float*)d_out;

    gru_warp_kernel<<<B, 32>>>(x, Wih0, Whh0, bih0, bhh0,
                               Wih1, Whh1, bih1, bhh1, Wlin, blin, out);
}

// round 5
// speedup vs baseline: 1.4125x; 1.4125x over previous
#include <cuda_runtime.h>
#include <cstddef>

// GRU_83133386982146: 2-layer GRU (H=10) + per-step linear 10->1.
// R3: (a) software-pipeline layer0(t+1) against layer1(t) (independent given
//     h0(t)); (b) replicate h0/h1 as full register vectors per lane so all
//     gate dots are local fma chains (shuffles only for r/z/n gather + h_new
//     broadcast); (c) output linear computed locally per lane (no warp reduce).
// One warp per batch row; 30 active lanes = 30 gate rows.

#define FULL 0xffffffffu

namespace {
constexpr int H = 10;
constexpr int G = 3 * H;   // 30 gate rows
constexpr int T = 2048;
constexpr int B = 1024;
}

__device__ __forceinline__ float fast_tanh(float x) {
    float y;
    asm("tanh.approx.f32 %0, %1;" : "=f"(y) : "f"(x));
    return y;
}
__device__ __forceinline__ float fast_sigmoid(float x) {
    // sigmoid(x) = 0.5 * tanh(0.5 x) + 0.5
    return fmaf(fast_tanh(0.5f * x), 0.5f, 0.5f);
}

__global__ void __launch_bounds__(32)
gru_warp_kernel(const float* __restrict__ x,
                const float* __restrict__ Wih0, const float* __restrict__ Whh0,
                const float* __restrict__ bih0, const float* __restrict__ bhh0,
                const float* __restrict__ Wih1, const float* __restrict__ Whh1,
                const float* __restrict__ bih1, const float* __restrict__ bhh1,
                const float* __restrict__ Wlin, const float* __restrict__ blin,
                float* __restrict__ out)
{
    const int b = blockIdx.x;
    const int lane = threadIdx.x;
    const int j = (lane < G) ? lane : (G - 1);   // clamp lanes 30,31
    const bool is_n = (j >= 2 * H);              // n-gate rows 20..29

    // Per-lane gate-row weights in registers.
    float whh0[H], wih1[H], whh1[H], wlinv[H];
#pragma unroll
    for (int k = 0; k < H; k++) {
        whh0[k]  = Whh0[j * H + k];
        wih1[k]  = Wih1[j * H + k];
        whh1[k]  = Whh1[j * H + k];
        wlinv[k] = Wlin[k];                      // full output row, all lanes
    }
    const float wih0 = Wih0[j];
    // r/z gates: fold bhh into the x-side bias; n gate: bhh stays in r*(...)
    const float bx0 = bih0[j] + (is_n ? 0.0f : bhh0[j]);
    const float bh0 = is_n ? bhh0[j] : 0.0f;
    const float bx1 = bih1[j] + (is_n ? 0.0f : bhh1[j]);
    const float bh1 = is_n ? bhh1[j] : 0.0f;
    const float bl = blin[0];

    const float* xrow = x + (size_t)b * T;
    float* orow = out + (size_t)b * T;

    // Replicated hidden states (static-indexed -> stay in registers).
    float h0v[H], h1v[H];
#pragma unroll
    for (int k = 0; k < H; k++) { h0v[k] = 0.0f; h1v[k] = 0.0f; }
    float h0own = 0.0f, h1own = 0.0f;            // lane k's own h_k (k<10)

    const int ridx = (lane >= 2 * H) ? (lane - 2 * H) : 0;  // n-lanes gather r
    const int zsrc = (lane + H) & 31;                       // lanes 0..9 gather z
    const int nsrc = (lane + 2 * H) & 31;                   // lanes 0..9 gather n

    float xbuf = xrow[lane];                     // first 32 timesteps
    float obuf = 0.0f;

    // ---- preamble: h0(0) (h0 state is zero => hidden dot = 0) ----
    {
        const float xt = __shfl_sync(FULL, xbuf, 0);
        const float a0 = bh0;
        const float p0 = fmaf(wih0, xt, bx0);
        const float s0 = fast_sigmoid(p0 + a0);
        const float r0 = __shfl_sync(FULL, s0, ridx);
        const float z0 = __shfl_sync(FULL, s0, zsrc);
        const float n0 = fast_tanh(fmaf(r0, a0, p0));
        const float nn0 = __shfl_sync(FULL, n0, nsrc);
        const float h0n = fmaf(z0, 0.0f - nn0, nn0);
        h0own = h0n;
#pragma unroll
        for (int k = 0; k < H; k++) h0v[k] = __shfl_sync(FULL, h0n, k);
    }

    // Loop invariant at top of iteration t:
    //   h0v/h0own = h0(t),  h1v/h1own = h1(t-1)
    // Body computes layer1(t) and layer0(t+1) concurrently.
    for (int t = 0; t < T; t++) {
        const int tn = t + 1;
        if (tn < T && (tn & 31) == 0) xbuf = xrow[tn + lane];   // coalesced
        const float xt1 = __shfl_sync(FULL, xbuf, tn & 31);

        // 6 independent local fma chains (2 per dot), depth 5.
        float a0a = bh0, a0b = 0.0f;     // layer0 hidden dot (for t+1)
        float axa = bx1, axb = 0.0f;     // layer1 input dot  (h0(t))
        float aha = bh1, ahb = 0.0f;     // layer1 hidden dot (h1(t-1))
#pragma unroll
        for (int k = 0; k < H; k += 2) {
            a0a = fmaf(whh0[k],     h0v[k],     a0a);
            axa = fmaf(wih1[k],     h0v[k],     axa);
            aha = fmaf(whh1[k],     h1v[k],     aha);
            a0b = fmaf(whh0[k + 1], h0v[k + 1], a0b);
            axb = fmaf(wih1[k + 1], h0v[k + 1], axb);
            ahb = fmaf(whh1[k + 1], h1v[k + 1], ahb);
        }
        const float a0 = a0a + a0b;
        const float ax = axa + axb;
        const float ah = aha + ahb;
        const float p0 = fmaf(wih0, xt1, bx0);

        // Both layers' gate chains run in parallel.
        const float s0 = fast_sigmoid(p0 + a0);
        const float s1 = fast_sigmoid(ax + ah);
        const float r0 = __shfl_sync(FULL, s0, ridx);
        const float r1 = __shfl_sync(FULL, s1, ridx);
        const float z0 = __shfl_sync(FULL, s0, zsrc);
        const float z1 = __shfl_sync(FULL, s1, zsrc);
        const float n0 = fast_tanh(fmaf(r0, a0, p0));
        const float n1 = fast_tanh(fmaf(r1, ah, ax));
        const float nn0 = __shfl_sync(FULL, n0, nsrc);
        const float nn1 = __shfl_sync(FULL, n1, nsrc);
        const float h0n = fmaf(z0, h0own - nn0, nn0);   // valid on lanes 0..9
        const float h1n = fmaf(z1, h1own - nn1, nn1);
        h0own = h0n;
        h1own = h1n;
#pragma unroll
        for (int k = 0; k < H; k++) {                   // 20 independent shfls
            h0v[k] = __shfl_sync(FULL, h0n, k);
            h1v[k] = __shfl_sync(FULL, h1n, k);
        }

        // Output(t) from h1(t): local dot, no warp reduce (redundant per lane).
        float ca = bl, cb = 0.0f;
#pragma unroll
        for (int k = 0; k < H; k += 2) {
            ca = fmaf(wlinv[k],     h1v[k],     ca);
            cb = fmaf(wlinv[k + 1], h1v[k + 1], cb);
        }
        const float val = ca + cb;
        if ((t & 31) == lane) obuf = val;
        if ((t & 31) == 31) orow[(t & ~31) + lane] = obuf;  // coalesced store
    }
}

extern "C" void kernel_launch(void* const* d_in, const int* in_sizes, int n_in,
                              void* d_out, int out_size) {
    (void)in_sizes; (void)n_in; (void)out_size;
    const float* x    = (const float*)d_in[0];
    const float* Wih0 = (const float*)d_in[1];
    const float* Whh0 = (const float*)d_in[2];
    const float* bih0 = (const float*)d_in[3];
    const float* bhh0 = (const float*)d_in[4];
    const float* Wih1 = (const float*)d_in[5];
    const float* Whh1 = (const float*)d_in[6];
    const float* bih1 = (const float*)d_in[7];
    const float* bhh1 = (const float*)d_in[8];
    const float* Wlin = (const float*)d_in[9];
    const float* blin = (const float*)d_in[10];
    float* out = (float*)d_out;

    gru_warp_kernel<<<B, 32>>>(x, Wih0, Whh0, bih0, bhh0,
                               Wih1, Whh1, bih1, bhh1, Wlin, blin, out);
}

// round 6
// speedup vs baseline: 1.9430x; 1.3755x over previous
#include <cuda_runtime.h>
#include <cstddef>

// GRU_83133386982146: 2-layer GRU (H=10) + per-step linear 10->1.
// R6: role-partitioned lanes, uniform instruction stream:
//   lanes  0- 9: layer0 unit k  (3 gate dots vs h0v; r/z/n + h0 update LOCAL)
//   lanes 10-19: layer1 ih dots (Wih1 rows . h0v)
//   lanes 20-29: layer1 hh dots (Whh1 rows . h1v) + layer1 gates + h1 update
// Combine ih+hh via 3 parallel shfls; state broadcast via 10 per-lane-source
// shfls (v[i] = shfl(hnew, base+i), base = 0 or 20). 15 shfls/step total.
// Software pipeline: iteration t computes h0(t+1) and h1(t) concurrently.

#define FULL 0xffffffffu

namespace {
constexpr int H = 10;
constexpr int T = 2048;
constexpr int B = 1024;
}

__device__ __forceinline__ float fast_tanh(float x) {
    float y;
    asm("tanh.approx.f32 %0, %1;" : "=f"(y) : "f"(x));
    return y;
}
__device__ __forceinline__ float fast_sigmoid(float x) {
    return fmaf(fast_tanh(0.5f * x), 0.5f, 0.5f);  // sig(x)=0.5*tanh(x/2)+0.5
}

__global__ void __launch_bounds__(32)
gru_warp_kernel(const float* __restrict__ x,
                const float* __restrict__ Wih0, const float* __restrict__ Whh0,
                const float* __restrict__ bih0, const float* __restrict__ bhh0,
                const float* __restrict__ Wih1, const float* __restrict__ Whh1,
                const float* __restrict__ bih1, const float* __restrict__ bhh1,
                const float* __restrict__ Wlin, const float* __restrict__ blin,
                float* __restrict__ out)
{
    const int b = blockIdx.x;
    const int lane = threadIdx.x;

    // ---- role assignment ----
    const bool isL0 = (lane < 10);                 // layer0 unit lanes
    const bool isIH = (lane >= 10 && lane < 20);   // layer1 input-side dots
    const bool isHH = (lane >= 20);                // layer1 hidden-side + gates
    const int  kk   = isL0 ? lane : (isIH ? lane - 10 : min(lane - 20, 9));

    const float* Wsrc = isL0 ? Whh0 : (isIH ? Wih1 : Whh1);

    // slot weight rows (A=r, B=z, C=n)
    float wa[H], wb[H], wc[H], wlinv[H];
#pragma unroll
    for (int i = 0; i < H; i++) {
        wa[i] = Wsrc[(kk) * H + i];
        wb[i] = Wsrc[(H + kk) * H + i];
        wc[i] = Wsrc[(2 * H + kk) * H + i];
        wlinv[i] = Wlin[i];
    }
    // x coefficients (layer0 only; input size 1)
    const float cxA = isL0 ? Wih0[kk] : 0.0f;
    const float cxB = isL0 ? Wih0[H + kk] : 0.0f;
    const float cxC = isL0 ? Wih0[2 * H + kk] : 0.0f;
    // dot seeds
    const float sA = isIH ? bih1[kk] : 0.0f;
    const float sB = isIH ? bih1[H + kk] : 0.0f;
    const float sC = isL0 ? bhh0[2 * H + kk]
                   : (isIH ? bih1[2 * H + kk] : bhh1[2 * H + kk]);
    // x-side / bias adds
    const float btA = isL0 ? (bih0[kk] + bhh0[kk]) : (isHH ? bhh1[kk] : 0.0f);
    const float btB = isL0 ? (bih0[H + kk] + bhh0[H + kk])
                           : (isHH ? bhh1[H + kk] : 0.0f);
    const float btC = isL0 ? bih0[2 * H + kk] : 0.0f;
    // combine selectors (only HH lanes add the shfl'd ih dots)
    const float sel = isHH ? 1.0f : 0.0f;
    const int   csrc = isHH ? (lane - 10) : lane;      // combine source lane
    const int   vbase = (lane < 20) ? 0 : 20;          // broadcast source base
    const float bl = blin[0];

    const float* xrow = x + (size_t)b * T;
    float* orow = out + (size_t)b * T;

    // v[i]: per-lane operand vector (h0v on lanes 0..19, h1v on lanes 20..31)
    float v[H];
#pragma unroll
    for (int i = 0; i < H; i++) v[i] = 0.0f;
    float hown = 0.0f;   // lane's own state: h0_k on L0 lanes, h1_k on HH lanes

    float xbuf = xrow[lane];     // first 32 timesteps
    float obuf = 0.0f;

    // ---- preamble: compute h0(0) on L0 lanes (h0(-1)=0, h1(-1)=0) ----
    {
        const float x0 = __shfl_sync(FULL, xbuf, 0);
        const float tA = fmaf(cxA, x0, btA);
        const float tB = fmaf(cxB, x0, btB);
        const float tC = fmaf(cxC, x0, btC);
        const float r = fast_sigmoid(tA);            // dots are 0 (sA only on IH)
        const float z = fast_sigmoid(tB);
        const float n = fast_tanh(fmaf(r, sC, tC));  // dotC seed = bhh0_n
        const float h0n = fmaf(z, 0.0f - n, n);      // valid on lanes 0..9
        hown = isL0 ? h0n : 0.0f;
        // broadcast: lanes needing h0v get it; h1v side stays zero
#pragma unroll
        for (int i = 0; i < H; i++) {
            const float t0 = __shfl_sync(FULL, h0n, i);
            v[i] = (lane < 20) ? t0 : 0.0f;
        }
    }

    // Invariant at loop top: v = h0(t) on lanes 0..19, h1(t-1) on lanes 20..31,
    // hown = h0(t)_k on L0 lanes, h1(t-1)_k on HH lanes.
    for (int t = 0; t < T; t++) {
        const int tn = t + 1;
        if (tn < T && (tn & 31) == 0) xbuf = xrow[tn + lane];   // coalesced
        const float xt1 = __shfl_sync(FULL, xbuf, tn & 31);

        // 6 independent fma chains (A/B/C x 2 partials), depth 5.
        float aA = sA, aB = sB, aC = sC;
        float bA2 = 0.0f, bB2 = 0.0f, bC2 = 0.0f;
#pragma unroll
        for (int i = 0; i < H; i += 2) {
            aA  = fmaf(wa[i],     v[i],     aA);
            aB  = fmaf(wb[i],     v[i],     aB);
            aC  = fmaf(wc[i],     v[i],     aC);
            bA2 = fmaf(wa[i + 1], v[i + 1], bA2);
            bB2 = fmaf(wb[i + 1], v[i + 1], bB2);
            bC2 = fmaf(wc[i + 1], v[i + 1], bC2);
        }
        const float dotA = aA + bA2;
        const float dotB = aB + bB2;
        const float dotC = aC + bC2;

        // combine: HH lanes pull the matching IH dots (parallel shfls)
        const float gA = __shfl_sync(FULL, dotA, csrc);
        const float gB = __shfl_sync(FULL, dotB, csrc);
        const float gC = __shfl_sync(FULL, dotC, csrc);

        const float tA = fmaf(cxA, xt1, btA);
        const float tB = fmaf(cxB, xt1, btB);
        const float tC = fmaf(cxC, xt1, btC);

        const float preA = fmaf(sel, gA, dotA + tA);
        const float preB = fmaf(sel, gB, dotB + tB);
        const float r = fast_sigmoid(preA);
        const float z = fast_sigmoid(preB);
        const float q = fmaf(sel, gC, tC);
        const float n = fast_tanh(fmaf(r, dotC, q));
        const float hnew = fmaf(z, hown - n, n);   // h0(t+1) on L0, h1(t) on HH
        hown = hnew;

        // broadcast: each lane rebuilds its operand vector directly
#pragma unroll
        for (int i = 0; i < H; i++)
            v[i] = __shfl_sync(FULL, hnew, vbase + i);

        // output(t) = Wlin . h1(t) + bl  (valid on lanes 20..31; v = h1v there)
        float ca = bl, cb = 0.0f;
#pragma unroll
        for (int i = 0; i < H; i += 2) {
            ca = fmaf(wlinv[i],     v[i],     ca);
            cb = fmaf(wlinv[i + 1], v[i + 1], cb);
        }
        const float val = __shfl_sync(FULL, ca + cb, 20);
        if ((t & 31) == lane) obuf = val;
        if ((t & 31) == 31) orow[(t & ~31) + lane] = obuf;  // coalesced store
    }
}

extern "C" void kernel_launch(void* const* d_in, const int* in_sizes, int n_in,
                              void* d_out, int out_size) {
    (void)in_sizes; (void)n_in; (void)out_size;
    const float* x    = (const float*)d_in[0];
    const float* Wih0 = (const float*)d_in[1];
    const float* Whh0 = (const float*)d_in[2];
    const float* bih0 = (const float*)d_in[3];
    const float* bhh0 = (const float*)d_in[4];
    const float* Wih1 = (const float*)d_in[5];
    const float* Whh1 = (const float*)d_in[6];
    const float* bih1 = (const float*)d_in[7];
    const float* bhh1 = (const float*)d_in[8];
    const float* Wlin = (const float*)d_in[9];
    const float* blin = (const float*)d_in[10];
    float* out = (float*)d_out;

    gru_warp_kernel<<<B, 32>>>(x, Wih0, Whh0, bih0, bhh0,
                               Wih1, Whh1, bih1, bhh1, Wlin, blin, out);
}